// round 1
// baseline (speedup 1.0000x reference)
#include <cuda_runtime.h>

#define N_NODES 2048
#define IN_F    512
#define HID     256
#define OUT_F   128
#define H1      8
#define F1      32   // HID / H1
#define NWORDS  64   // N_NODES / 32

// ---------------- scratch (static device globals; no allocation) ----------------
__device__ float    g_g1[N_NODES * HID];       // x @ W1
__device__ float    g_el1[N_NODES * H1];
__device__ float    g_er1[N_NODES * H1];
__device__ unsigned g_bits[N_NODES * NWORDS];  // packed adjacency
__device__ float    g_h1[N_NODES * HID];       // elu(layer1 out)
__device__ float    g_g2[N_NODES * OUT_F];     // h1 @ W2
__device__ float    g_el2[N_NODES];
__device__ float    g_er2[N_NODES];
__device__ float    g_part[8 * N_NODES * OUT_F]; // layer2 partial numerators
__device__ float    g_psum[8 * N_NODES];         // layer2 partial denominators

// ---------------- pack adjacency into bitmask ----------------
__global__ void pack_adj_kernel(const int* __restrict__ adj) {
    int i = blockIdx.x;
    int t = threadIdx.x;  // 256
    const int* row = adj + (size_t)i * N_NODES;
#pragma unroll
    for (int k = 0; k < 8; k++) {
        int j = k * 256 + t;
        unsigned b = __ballot_sync(0xffffffffu, row[j] != 0);
        if ((t & 31) == 0) g_bits[i * NWORDS + (j >> 5)] = b;
    }
}

// ---------------- generic fp32 tiled GEMM: C[M,N] = A[M,K] @ B[K,N] ----------------
// 256 threads, 64x64 tile, 4x4 per thread.
template <int BM, int BN, int BK>
__global__ void gemm_kernel(const float* __restrict__ A, const float* __restrict__ B,
                            float* __restrict__ C, int M, int N, int K) {
    __shared__ float As[BM][BK + 1];
    __shared__ __align__(16) float Bs[BK][BN];
    int bi = blockIdx.y * BM;
    int bn = blockIdx.x * BN;
    int t = threadIdx.x;
    int tn = (t % (BN / 4)) * 4;
    int ti = (t / (BN / 4)) * 4;
    float acc[4][4] = {};
    for (int k0 = 0; k0 < K; k0 += BK) {
        for (int e = t; e < BM * BK; e += 256) {
            int i = e / BK, k = e % BK;
            As[i][k] = A[(size_t)(bi + i) * K + k0 + k];
        }
        for (int e = t; e < BK * BN; e += 256) {
            int k = e / BN, n = e % BN;
            Bs[k][n] = B[(size_t)(k0 + k) * N + bn + n];
        }
        __syncthreads();
#pragma unroll
        for (int k = 0; k < BK; k++) {
            float a0 = As[ti + 0][k];
            float a1 = As[ti + 1][k];
            float a2 = As[ti + 2][k];
            float a3 = As[ti + 3][k];
            float4 b = *(const float4*)&Bs[k][tn];
            acc[0][0] = fmaf(a0, b.x, acc[0][0]); acc[0][1] = fmaf(a0, b.y, acc[0][1]);
            acc[0][2] = fmaf(a0, b.z, acc[0][2]); acc[0][3] = fmaf(a0, b.w, acc[0][3]);
            acc[1][0] = fmaf(a1, b.x, acc[1][0]); acc[1][1] = fmaf(a1, b.y, acc[1][1]);
            acc[1][2] = fmaf(a1, b.z, acc[1][2]); acc[1][3] = fmaf(a1, b.w, acc[1][3]);
            acc[2][0] = fmaf(a2, b.x, acc[2][0]); acc[2][1] = fmaf(a2, b.y, acc[2][1]);
            acc[2][2] = fmaf(a2, b.z, acc[2][2]); acc[2][3] = fmaf(a2, b.w, acc[2][3]);
            acc[3][0] = fmaf(a3, b.x, acc[3][0]); acc[3][1] = fmaf(a3, b.y, acc[3][1]);
            acc[3][2] = fmaf(a3, b.z, acc[3][2]); acc[3][3] = fmaf(a3, b.w, acc[3][3]);
        }
        __syncthreads();
    }
#pragma unroll
    for (int r = 0; r < 4; r++)
#pragma unroll
        for (int c = 0; c < 4; c++)
            C[(size_t)(bi + ti + r) * N + bn + tn + c] = acc[r][c];
}

// ---------------- layer1 el/er: per-head 32-dot products ----------------
__global__ void elr1_kernel(const float* __restrict__ al, const float* __restrict__ ar) {
    int i = blockIdx.x;
    int t = threadIdx.x;  // 256
    float v = g_g1[i * HID + t];
    float pl = v * al[t & 31];
    float pr = v * ar[t & 31];
#pragma unroll
    for (int o = 16; o; o >>= 1) {
        pl += __shfl_down_sync(0xffffffffu, pl, o);
        pr += __shfl_down_sync(0xffffffffu, pr, o);
    }
    if ((t & 31) == 0) {
        g_el1[i * H1 + (t >> 5)] = pl;
        g_er1[i * H1 + (t >> 5)] = pr;
    }
}

// ---------------- layer1 aggregation: per head, 128-row tile ----------------
// out[i, h*32+f] = elu( (sum_j w(i,j) * g1[j, h*32+f]) / sum_j w(i,j) )
// w(i,j) = adj(i,j) ? exp(lrelu(el[i]+er[j])) : 0   (scores bounded, no max shift needed)
__global__ void agg1_kernel() {
    __shared__ __align__(16) float w_s[64][128];   // [j][i], transposed for vec reads
    __shared__ __align__(16) float G_s[64][F1];
    __shared__ float el_s[128];
    __shared__ float rowsum_s[128];
    int h = blockIdx.x;
    int bi = blockIdx.y * 128;
    int t = threadIdx.x;  // 256
    if (t < 128) {
        el_s[t] = g_el1[(bi + t) * H1 + h];
        rowsum_s[t] = 0.f;
    }
    __syncthreads();

    int wi = t & 127;       // weight-phase row
    int whalf = t >> 7;     // which 32-j half
    int f0 = (t & 7) * 4;   // fma-phase feature quad
    int i0 = (t >> 3) * 4;  // fma-phase row quad
    float acc[4][4] = {};
    float el = el_s[wi];

    for (int j0 = 0; j0 < N_NODES; j0 += 64) {
        // load G chunk [64 j][32 f]
        for (int e = t; e < 64 * F1; e += 256) {
            int j = e >> 5, f = e & 31;
            G_s[j][f] = g_g1[(size_t)(j0 + j) * HID + h * F1 + f];
        }
        // compute weight chunk [64 j][128 i]
        unsigned word = g_bits[(bi + wi) * NWORDS + (j0 >> 5) + whalf];
        int jb = whalf * 32;
        float lsum = 0.f;
#pragma unroll
        for (int jj = 0; jj < 32; jj++) {
            float er = g_er1[(j0 + jb + jj) * H1 + h];  // uniform per warp, L1 hit
            float s = el + er;
            float lr = s > 0.f ? s : 0.2f * s;
            float w = ((word >> jj) & 1u) ? __expf(lr) : 0.f;
            lsum += w;
            w_s[jb + jj][wi] = w;
        }
        atomicAdd(&rowsum_s[wi], lsum);
        __syncthreads();
        // FMA phase: 16 FMA per 32B of LDS
#pragma unroll 8
        for (int jj = 0; jj < 64; jj++) {
            float4 w4 = *(const float4*)&w_s[jj][i0];
            float4 g4 = *(const float4*)&G_s[jj][f0];
            acc[0][0] = fmaf(w4.x, g4.x, acc[0][0]); acc[0][1] = fmaf(w4.x, g4.y, acc[0][1]);
            acc[0][2] = fmaf(w4.x, g4.z, acc[0][2]); acc[0][3] = fmaf(w4.x, g4.w, acc[0][3]);
            acc[1][0] = fmaf(w4.y, g4.x, acc[1][0]); acc[1][1] = fmaf(w4.y, g4.y, acc[1][1]);
            acc[1][2] = fmaf(w4.y, g4.z, acc[1][2]); acc[1][3] = fmaf(w4.y, g4.w, acc[1][3]);
            acc[2][0] = fmaf(w4.z, g4.x, acc[2][0]); acc[2][1] = fmaf(w4.z, g4.y, acc[2][1]);
            acc[2][2] = fmaf(w4.z, g4.z, acc[2][2]); acc[2][3] = fmaf(w4.z, g4.w, acc[2][3]);
            acc[3][0] = fmaf(w4.w, g4.x, acc[3][0]); acc[3][1] = fmaf(w4.w, g4.y, acc[3][1]);
            acc[3][2] = fmaf(w4.w, g4.z, acc[3][2]); acc[3][3] = fmaf(w4.w, g4.w, acc[3][3]);
        }
        __syncthreads();
    }
#pragma unroll
    for (int r = 0; r < 4; r++) {
        float inv = 1.f / rowsum_s[i0 + r];
#pragma unroll
        for (int c = 0; c < 4; c++) {
            float o = acc[r][c] * inv;
            g_h1[(size_t)(bi + i0 + r) * HID + h * F1 + f0 + c] = o > 0.f ? o : expm1f(o);
        }
    }
}

// ---------------- layer2 el/er: 128-dot products ----------------
__global__ void elr2_kernel(const float* __restrict__ al, const float* __restrict__ ar) {
    __shared__ float sl[4], sr[4];
    int i = blockIdx.x;
    int t = threadIdx.x;  // 128
    float v = g_g2[i * OUT_F + t];
    float pl = v * al[t];
    float pr = v * ar[t];
#pragma unroll
    for (int o = 16; o; o >>= 1) {
        pl += __shfl_down_sync(0xffffffffu, pl, o);
        pr += __shfl_down_sync(0xffffffffu, pr, o);
    }
    if ((t & 31) == 0) { sl[t >> 5] = pl; sr[t >> 5] = pr; }
    __syncthreads();
    if (t == 0) g_el2[i] = sl[0] + sl[1] + sl[2] + sl[3];
    if (t == 1) g_er2[i] = sr[0] + sr[1] + sr[2] + sr[3];
}

// ---------------- layer2 aggregation: 64-row tile, 8-way j-split partials ----------------
__global__ void agg2_kernel() {
    __shared__ __align__(16) float w_s[32][64];
    __shared__ __align__(16) float G_s[32][OUT_F];
    __shared__ float el_s[64];
    __shared__ float rowsum_s[64];
    int p = blockIdx.x;        // j partition 0..7
    int bi = blockIdx.y * 64;  // row tile
    int t = threadIdx.x;       // 256
    if (t < 64) {
        el_s[t] = g_el2[bi + t];
        rowsum_s[t] = 0.f;
    }
    __syncthreads();

    int wi = t & 63;
    int wq = t >> 6;            // 0..3, 8 j's each
    int f0 = (t & 15) * 8;
    int i0 = (t >> 4) * 4;
    float acc[4][8] = {};
    float el = el_s[wi];
    int jstart = p * 256;

    for (int j0 = jstart; j0 < jstart + 256; j0 += 32) {
        for (int e = t; e < 32 * OUT_F; e += 256) {
            int j = e >> 7, f = e & 127;
            G_s[j][f] = g_g2[(size_t)(j0 + j) * OUT_F + f];
        }
        unsigned word = g_bits[(bi + wi) * NWORDS + (j0 >> 5)];
        int jb = wq * 8;
        float lsum = 0.f;
#pragma unroll
        for (int jj = 0; jj < 8; jj++) {
            float er = g_er2[j0 + jb + jj];  // uniform per warp
            float s = el + er;
            float lr = s > 0.f ? s : 0.2f * s;
            float w = ((word >> (jb + jj)) & 1u) ? __expf(lr) : 0.f;
            lsum += w;
            w_s[jb + jj][wi] = w;
        }
        atomicAdd(&rowsum_s[wi], lsum);
        __syncthreads();
#pragma unroll 4
        for (int jj = 0; jj < 32; jj++) {
            float4 w4 = *(const float4*)&w_s[jj][i0];
            float4 ga = *(const float4*)&G_s[jj][f0];
            float4 gb = *(const float4*)&G_s[jj][f0 + 4];
            float wv[4] = {w4.x, w4.y, w4.z, w4.w};
            float gv[8] = {ga.x, ga.y, ga.z, ga.w, gb.x, gb.y, gb.z, gb.w};
#pragma unroll
            for (int r = 0; r < 4; r++)
#pragma unroll
                for (int c = 0; c < 8; c++)
                    acc[r][c] = fmaf(wv[r], gv[c], acc[r][c]);
        }
        __syncthreads();
    }
    // write deterministic partials (no global float atomics)
#pragma unroll
    for (int r = 0; r < 4; r++)
#pragma unroll
        for (int c = 0; c < 8; c++)
            g_part[(size_t)p * N_NODES * OUT_F + (size_t)(bi + i0 + r) * OUT_F + f0 + c] = acc[r][c];
    if (t < 64) g_psum[p * N_NODES + bi + t] = rowsum_s[t];
}

// ---------------- final reduce + divide ----------------
__global__ void reduce2_kernel(float* __restrict__ out) {
    int i = blockIdx.x;
    int f = threadIdx.x;  // 128
    float num = 0.f, den = 0.f;
#pragma unroll
    for (int p = 0; p < 8; p++) {
        num += g_part[(size_t)p * N_NODES * OUT_F + (size_t)i * OUT_F + f];
        den += g_psum[p * N_NODES + i];
    }
    out[i * OUT_F + f] = num / den;
}

// ---------------- launch ----------------
extern "C" void kernel_launch(void* const* d_in, const int* in_sizes, int n_in,
                              void* d_out, int out_size) {
    const float* x    = (const float*)d_in[0];
    const float* W1   = (const float*)d_in[1];
    const float* a1_l = (const float*)d_in[2];
    const float* a1_r = (const float*)d_in[3];
    const float* W2   = (const float*)d_in[4];
    const float* a2_l = (const float*)d_in[5];
    const float* a2_r = (const float*)d_in[6];
    const int*   adj  = (const int*)d_in[7];
    float* out = (float*)d_out;

    float* g1 = nullptr; float* h1 = nullptr; float* g2 = nullptr;
    cudaGetSymbolAddress((void**)&g1, g_g1);
    cudaGetSymbolAddress((void**)&h1, g_h1);
    cudaGetSymbolAddress((void**)&g2, g_g2);

    pack_adj_kernel<<<N_NODES, 256>>>(adj);
    gemm_kernel<64, 64, 16><<<dim3(HID / 64, N_NODES / 64), 256>>>(x, W1, g1, N_NODES, HID, IN_F);
    elr1_kernel<<<N_NODES, 256>>>(a1_l, a1_r);
    agg1_kernel<<<dim3(H1, N_NODES / 128), 256>>>();
    gemm_kernel<64, 64, 16><<<dim3(OUT_F / 64, N_NODES / 64), 256>>>(h1, W2, g2, N_NODES, OUT_F, HID);
    elr2_kernel<<<N_NODES, 128>>>(a2_l, a2_r);
    agg2_kernel<<<dim3(8, N_NODES / 64), 256>>>();
    reduce2_kernel<<<N_NODES, 128>>>(out);
}

// round 2
// speedup vs baseline: 2.1037x; 2.1037x over previous
#include <cuda_runtime.h>

#define N_NODES 2048
#define IN_F    512
#define HID     256
#define OUT_F   128
#define H1      8
#define F1      32   // HID / H1
#define NWORDS  64   // N_NODES / 32

// ---------------- scratch (static device globals; no allocation) ----------------
__device__ __align__(16) float    g_g1[N_NODES * HID];       // x @ W1
__device__ __align__(16) float4   g_eli1[N_NODES * H1];      // {-el, exp(el), exp(0.2el), 0}
__device__ __align__(16) float4   g_ebd1[N_NODES * H1];      // {er, exp(er), exp(0.2er), 0}
__device__ unsigned g_bits[N_NODES * NWORDS];                // packed adjacency
__device__ __align__(16) float    g_n1[2 * N_NODES * HID];   // layer1 partial numerators
__device__ float    g_d1[2 * N_NODES * H1];                  // layer1 partial denominators
__device__ __align__(16) float    g_h1[N_NODES * HID];       // elu(layer1 out)
__device__ __align__(16) float    g_g2[N_NODES * OUT_F];     // h1 @ W2
__device__ __align__(16) float4   g_eli2[N_NODES];
__device__ __align__(16) float4   g_ebd2[N_NODES];
__device__ __align__(16) float    g_part[8 * N_NODES * OUT_F]; // layer2 partial numerators
__device__ float    g_psum[8 * N_NODES];                       // layer2 partial denominators

// ---------------- pack adjacency into bitmask ----------------
__global__ void pack_adj_kernel(const int* __restrict__ adj) {
    int i = blockIdx.x;
    int t = threadIdx.x;  // 256
    const int* row = adj + (size_t)i * N_NODES;
#pragma unroll
    for (int k = 0; k < 8; k++) {
        int j = k * 256 + t;
        unsigned b = __ballot_sync(0xffffffffu, row[j] != 0);
        if ((t & 31) == 0) g_bits[i * NWORDS + (j >> 5)] = b;
    }
}

// ---------------- generic fp32 tiled GEMM: C[M,N] = A[M,K] @ B[K,N] ----------------
template <int BM, int BN, int BK>
__global__ __launch_bounds__(256) void gemm_kernel(const float* __restrict__ A,
                                                   const float* __restrict__ B,
                                                   float* __restrict__ C, int M, int N, int K) {
    __shared__ float As[BM][BK + 1];
    __shared__ __align__(16) float Bs[BK][BN];
    int bi = blockIdx.y * BM;
    int bn = blockIdx.x * BN;
    int t = threadIdx.x;
    int tn = (t % (BN / 4)) * 4;
    int ti = (t / (BN / 4)) * 4;
    float acc[4][4] = {};
    for (int k0 = 0; k0 < K; k0 += BK) {
        for (int e = t; e < BM * BK; e += 256) {
            int i = e / BK, k = e % BK;
            As[i][k] = A[(size_t)(bi + i) * K + k0 + k];
        }
        for (int e = t; e < BK * BN; e += 256) {
            int k = e / BN, n = e % BN;
            Bs[k][n] = B[(size_t)(k0 + k) * N + bn + n];
        }
        __syncthreads();
#pragma unroll
        for (int k = 0; k < BK; k++) {
            float a0 = As[ti + 0][k];
            float a1 = As[ti + 1][k];
            float a2 = As[ti + 2][k];
            float a3 = As[ti + 3][k];
            float4 b = *(const float4*)&Bs[k][tn];
            acc[0][0] = fmaf(a0, b.x, acc[0][0]); acc[0][1] = fmaf(a0, b.y, acc[0][1]);
            acc[0][2] = fmaf(a0, b.z, acc[0][2]); acc[0][3] = fmaf(a0, b.w, acc[0][3]);
            acc[1][0] = fmaf(a1, b.x, acc[1][0]); acc[1][1] = fmaf(a1, b.y, acc[1][1]);
            acc[1][2] = fmaf(a1, b.z, acc[1][2]); acc[1][3] = fmaf(a1, b.w, acc[1][3]);
            acc[2][0] = fmaf(a2, b.x, acc[2][0]); acc[2][1] = fmaf(a2, b.y, acc[2][1]);
            acc[2][2] = fmaf(a2, b.z, acc[2][2]); acc[2][3] = fmaf(a2, b.w, acc[2][3]);
            acc[3][0] = fmaf(a3, b.x, acc[3][0]); acc[3][1] = fmaf(a3, b.y, acc[3][1]);
            acc[3][2] = fmaf(a3, b.z, acc[3][2]); acc[3][3] = fmaf(a3, b.w, acc[3][3]);
        }
        __syncthreads();
    }
#pragma unroll
    for (int r = 0; r < 4; r++)
#pragma unroll
        for (int c = 0; c < 4; c++)
            C[(size_t)(bi + ti + r) * N + bn + tn + c] = acc[r][c];
}

// ---------------- layer1 el/er + per-node exponentials ----------------
__global__ void elr1_kernel(const float* __restrict__ al, const float* __restrict__ ar) {
    int i = blockIdx.x;
    int t = threadIdx.x;  // 256: warp h handles head h
    float v = g_g1[i * HID + t];
    float pl = v * al[t & 31];
    float pr = v * ar[t & 31];
#pragma unroll
    for (int o = 16; o; o >>= 1) {
        pl += __shfl_down_sync(0xffffffffu, pl, o);
        pr += __shfl_down_sync(0xffffffffu, pr, o);
    }
    if ((t & 31) == 0) {
        int h = t >> 5;
        float el = pl, er = pr;
        g_eli1[i * H1 + h] = make_float4(-el, __expf(el), __expf(0.2f * el), 0.f);
        g_ebd1[i * H1 + h] = make_float4(er, __expf(er), __expf(0.2f * er), 0.f);
    }
}

// ---------------- layer1 aggregation (no exp in inner loop) ----------------
// w(i,j) = adj ? ((el_i+er_j>0) ? A_i*B_j : C_i*D_j) : 0
__global__ __launch_bounds__(256) void agg1_kernel() {
    __shared__ __align__(16) float w_s[64][128];   // [j][i]
    __shared__ __align__(16) float G_s[64][F1];
    __shared__ float rowsum_s[128];
    int h = blockIdx.x >> 1;
    int p = blockIdx.x & 1;
    int bi = blockIdx.y * 128;
    int t = threadIdx.x;  // 256
    if (t < 128) rowsum_s[t] = 0.f;

    int wi = t & 127;       // weight-phase row
    int whalf = t >> 7;     // which 32-j half
    float4 eli = g_eli1[(bi + wi) * H1 + h];
    float negEl = eli.x, Ai = eli.y, Ci = eli.z;
    int f0 = (t & 7) * 4;
    int i0 = (t >> 3) * 4;
    float acc[4][4] = {};
    float lsum = 0.f;
    int jstart = p * 1024;

    for (int j0 = jstart; j0 < jstart + 1024; j0 += 64) {
        __syncthreads();  // previous-iter FMA readers done with w_s/G_s
        // load G chunk [64 j][32 f] as float4
#pragma unroll
        for (int e = t; e < 512; e += 256) {
            int j = e >> 3, q = e & 7;
            ((float4*)G_s[j])[q] = ((const float4*)(g_g1 + (size_t)(j0 + j) * HID + h * F1))[q];
        }
        // weight chunk [64 j][128 i]: no MUFU — separable exp
        unsigned word = g_bits[(bi + wi) * NWORDS + (j0 >> 5) + whalf];
        int jb = whalf * 32;
#pragma unroll 8
        for (int jj = 0; jj < 32; jj++) {
            float4 e4 = g_ebd1[(size_t)(j0 + jb + jj) * H1 + h];  // uniform per warp
            float w = (e4.x > negEl) ? Ai * e4.y : Ci * e4.z;
            w = ((word >> jj) & 1u) ? w : 0.f;
            lsum += w;
            w_s[jb + jj][wi] = w;
        }
        __syncthreads();
        // FMA phase: 16 FMA per 32B of LDS
#pragma unroll 8
        for (int jj = 0; jj < 64; jj++) {
            float4 w4 = *(const float4*)&w_s[jj][i0];
            float4 g4 = *(const float4*)&G_s[jj][f0];
            acc[0][0] = fmaf(w4.x, g4.x, acc[0][0]); acc[0][1] = fmaf(w4.x, g4.y, acc[0][1]);
            acc[0][2] = fmaf(w4.x, g4.z, acc[0][2]); acc[0][3] = fmaf(w4.x, g4.w, acc[0][3]);
            acc[1][0] = fmaf(w4.y, g4.x, acc[1][0]); acc[1][1] = fmaf(w4.y, g4.y, acc[1][1]);
            acc[1][2] = fmaf(w4.y, g4.z, acc[1][2]); acc[1][3] = fmaf(w4.y, g4.w, acc[1][3]);
            acc[2][0] = fmaf(w4.z, g4.x, acc[2][0]); acc[2][1] = fmaf(w4.z, g4.y, acc[2][1]);
            acc[2][2] = fmaf(w4.z, g4.z, acc[2][2]); acc[2][3] = fmaf(w4.z, g4.w, acc[2][3]);
            acc[3][0] = fmaf(w4.w, g4.x, acc[3][0]); acc[3][1] = fmaf(w4.w, g4.y, acc[3][1]);
            acc[3][2] = fmaf(w4.w, g4.z, acc[3][2]); acc[3][3] = fmaf(w4.w, g4.w, acc[3][3]);
        }
    }
    atomicAdd(&rowsum_s[wi], lsum);
    __syncthreads();

    size_t base = (size_t)p * N_NODES + bi;
#pragma unroll
    for (int r = 0; r < 4; r++)
#pragma unroll
        for (int c = 0; c < 4; c++)
            g_n1[(base + i0 + r) * HID + h * F1 + f0 + c] = acc[r][c];
    if (t < 128) g_d1[(base + t) * H1 + h] = rowsum_s[t];
}

// ---------------- layer1 reduce + divide + ELU ----------------
__global__ void reduce1_kernel() {
    int i = blockIdx.x;
    int t = threadIdx.x;  // 256
    int h = t >> 5;
    float num = g_n1[(size_t)i * HID + t] + g_n1[(size_t)(N_NODES + i) * HID + t];
    float den = g_d1[i * H1 + h] + g_d1[(N_NODES + i) * H1 + h];
    float o = num / den;
    g_h1[(size_t)i * HID + t] = o > 0.f ? o : expm1f(o);
}

// ---------------- layer2 el/er + exponentials ----------------
__global__ void elr2_kernel(const float* __restrict__ al, const float* __restrict__ ar) {
    __shared__ float sl[4], sr[4];
    int i = blockIdx.x;
    int t = threadIdx.x;  // 128
    float v = g_g2[i * OUT_F + t];
    float pl = v * al[t];
    float pr = v * ar[t];
#pragma unroll
    for (int o = 16; o; o >>= 1) {
        pl += __shfl_down_sync(0xffffffffu, pl, o);
        pr += __shfl_down_sync(0xffffffffu, pr, o);
    }
    if ((t & 31) == 0) { sl[t >> 5] = pl; sr[t >> 5] = pr; }
    __syncthreads();
    if (t == 0) {
        float el = sl[0] + sl[1] + sl[2] + sl[3];
        float er = sr[0] + sr[1] + sr[2] + sr[3];
        g_eli2[i] = make_float4(-el, __expf(el), __expf(0.2f * el), 0.f);
        g_ebd2[i] = make_float4(er, __expf(er), __expf(0.2f * er), 0.f);
    }
}

// ---------------- layer2 aggregation: 64-row tile, 8-way j-split ----------------
__global__ __launch_bounds__(256) void agg2_kernel() {
    __shared__ __align__(16) float w_s[32][64];
    __shared__ __align__(16) float G_s[32][OUT_F];
    __shared__ float rowsum_s[64];
    int p = blockIdx.x;        // j partition 0..7
    int bi = blockIdx.y * 64;  // row tile
    int t = threadIdx.x;       // 256
    if (t < 64) rowsum_s[t] = 0.f;

    int wi = t & 63;
    int wq = t >> 6;            // 0..3, 8 j's each
    float4 eli = g_eli2[bi + wi];
    float negEl = eli.x, Ai = eli.y, Ci = eli.z;
    int f0 = (t & 15) * 8;
    int i0 = (t >> 4) * 4;
    float acc[4][8] = {};
    float lsum = 0.f;
    int jstart = p * 256;

    for (int j0 = jstart; j0 < jstart + 256; j0 += 32) {
        __syncthreads();
#pragma unroll
        for (int e = t; e < 1024; e += 256) {
            int j = e >> 5, q = e & 31;
            ((float4*)G_s[j])[q] = ((const float4*)(g_g2 + (size_t)(j0 + j) * OUT_F))[q];
        }
        unsigned word = g_bits[(bi + wi) * NWORDS + (j0 >> 5)];
        int jb = wq * 8;
#pragma unroll
        for (int jj = 0; jj < 8; jj++) {
            float4 e4 = g_ebd2[j0 + jb + jj];  // uniform per warp
            float w = (e4.x > negEl) ? Ai * e4.y : Ci * e4.z;
            w = ((word >> (jb + jj)) & 1u) ? w : 0.f;
            lsum += w;
            w_s[jb + jj][wi] = w;
        }
        __syncthreads();
#pragma unroll 4
        for (int jj = 0; jj < 32; jj++) {
            float4 w4 = *(const float4*)&w_s[jj][i0];
            float4 ga = *(const float4*)&G_s[jj][f0];
            float4 gb = *(const float4*)&G_s[jj][f0 + 4];
            float wv[4] = {w4.x, w4.y, w4.z, w4.w};
            float gv[8] = {ga.x, ga.y, ga.z, ga.w, gb.x, gb.y, gb.z, gb.w};
#pragma unroll
            for (int r = 0; r < 4; r++)
#pragma unroll
                for (int c = 0; c < 8; c++)
                    acc[r][c] = fmaf(wv[r], gv[c], acc[r][c]);
        }
    }
    atomicAdd(&rowsum_s[wi], lsum);
    __syncthreads();

#pragma unroll
    for (int r = 0; r < 4; r++)
#pragma unroll
        for (int c = 0; c < 8; c++)
            g_part[(size_t)p * N_NODES * OUT_F + (size_t)(bi + i0 + r) * OUT_F + f0 + c] = acc[r][c];
    if (t < 64) g_psum[p * N_NODES + bi + t] = rowsum_s[t];
}

// ---------------- final reduce + divide ----------------
__global__ void reduce2_kernel(float* __restrict__ out) {
    int i = blockIdx.x;
    int f = threadIdx.x;  // 128
    float num = 0.f, den = 0.f;
#pragma unroll
    for (int p = 0; p < 8; p++) {
        num += g_part[(size_t)p * N_NODES * OUT_F + (size_t)i * OUT_F + f];
        den += g_psum[p * N_NODES + i];
    }
    out[i * OUT_F + f] = num / den;
}

// ---------------- launch ----------------
extern "C" void kernel_launch(void* const* d_in, const int* in_sizes, int n_in,
                              void* d_out, int out_size) {
    const float* x    = (const float*)d_in[0];
    const float* W1   = (const float*)d_in[1];
    const float* a1_l = (const float*)d_in[2];
    const float* a1_r = (const float*)d_in[3];
    const float* W2   = (const float*)d_in[4];
    const float* a2_l = (const float*)d_in[5];
    const float* a2_r = (const float*)d_in[6];
    const int*   adj  = (const int*)d_in[7];
    float* out = (float*)d_out;

    float* g1 = nullptr; float* h1 = nullptr; float* g2 = nullptr;
    cudaGetSymbolAddress((void**)&g1, g_g1);
    cudaGetSymbolAddress((void**)&h1, g_h1);
    cudaGetSymbolAddress((void**)&g2, g_g2);

    pack_adj_kernel<<<N_NODES, 256>>>(adj);
    gemm_kernel<64, 64, 16><<<dim3(HID / 64, N_NODES / 64), 256>>>(x, W1, g1, N_NODES, HID, IN_F);
    elr1_kernel<<<N_NODES, 256>>>(a1_l, a1_r);
    agg1_kernel<<<dim3(H1 * 2, N_NODES / 128), 256>>>();
    reduce1_kernel<<<N_NODES, 256>>>();
    gemm_kernel<64, 64, 16><<<dim3(OUT_F / 64, N_NODES / 64), 256>>>(h1, W2, g2, N_NODES, OUT_F, HID);
    elr2_kernel<<<N_NODES, 128>>>(a2_l, a2_r);
    agg2_kernel<<<dim3(8, N_NODES / 64), 256>>>();
    reduce2_kernel<<<N_NODES, 128>>>(out);
}

// round 3
// speedup vs baseline: 2.5271x; 1.2013x over previous
#include <cuda_runtime.h>

#define N_NODES 2048
#define IN_F    512
#define HID     256
#define OUT_F   128
#define H1      8
#define F1      32   // HID / H1
#define NWORDS  64   // N_NODES / 32
#define JSPLIT1 4
#define JSPLIT2 8

typedef unsigned long long ull;

__device__ __forceinline__ ull fma2(ull a, ull b, ull c) {
    ull d;
    asm("fma.rn.f32x2 %0, %1, %2, %3;" : "=l"(d) : "l"(a), "l"(b), "l"(c));
    return d;
}
__device__ __forceinline__ ull pack2(float v) {
    ull d;
    asm("mov.b64 %0, {%1, %1};" : "=l"(d) : "f"(v));
    return d;
}
__device__ __forceinline__ void unpack2(ull v, float& lo, float& hi) {
    asm("mov.b64 {%0, %1}, %2;" : "=f"(lo), "=f"(hi) : "l"(v));
}

// ---------------- scratch (static device globals; no allocation) ----------------
__device__ __align__(16) float    g_gp1[2 * N_NODES * HID];    // gemm1 K-split partials
__device__ __align__(16) float    g_g1[N_NODES * HID];         // x @ W1
__device__ __align__(16) float4   g_eli1[N_NODES * H1];        // {-el, exp(el), exp(0.2el), 0}
__device__ __align__(16) float4   g_ebd1[N_NODES * H1];        // {er, exp(er), exp(0.2er), 0}
__device__ unsigned g_bits[N_NODES * NWORDS];                  // packed adjacency
__device__ __align__(16) float    g_n1[JSPLIT1 * N_NODES * HID]; // layer1 partial numerators
__device__ float    g_d1[JSPLIT1 * N_NODES * H1];                // layer1 partial denominators
__device__ __align__(16) float    g_h1[N_NODES * HID];         // elu(layer1 out)
__device__ __align__(16) float    g_gp2[2 * N_NODES * OUT_F];  // gemm2 K-split partials
__device__ __align__(16) float    g_g2[N_NODES * OUT_F];       // h1 @ W2
__device__ __align__(16) float4   g_eli2[N_NODES];
__device__ __align__(16) float4   g_ebd2[N_NODES];
__device__ __align__(16) float    g_part[JSPLIT2 * N_NODES * OUT_F];
__device__ float    g_psum[JSPLIT2 * N_NODES];

// ---------------- pack adjacency into bitmask ----------------
__global__ void pack_adj_kernel(const int* __restrict__ adj) {
    int i = blockIdx.x;
    int t = threadIdx.x;  // 256
    const int* row = adj + (size_t)i * N_NODES;
#pragma unroll
    for (int k = 0; k < 8; k++) {
        int j = k * 256 + t;
        unsigned b = __ballot_sync(0xffffffffu, row[j] != 0);
        if ((t & 31) == 0) g_bits[i * NWORDS + (j >> 5)] = b;
    }
}

// ---------------- fp32 tiled GEMM with K-split via blockIdx.z ----------------
// Cpart[z][M,N] = A[:, z*Klen:(z+1)*Klen] @ B[z*Klen:(z+1)*Klen, :]
template <int BM, int BN, int BK>
__global__ __launch_bounds__(256) void gemm_kernel(const float* __restrict__ A,
                                                   const float* __restrict__ B,
                                                   float* __restrict__ C,
                                                   int M, int N, int Klen, int lda) {
    __shared__ float As[BM][BK + 1];
    __shared__ __align__(16) float Bs[BK][BN];
    const float* Ap = A + (size_t)blockIdx.z * Klen;
    const float* Bp = B + (size_t)blockIdx.z * Klen * N;
    float* Cp = C + (size_t)blockIdx.z * M * N;
    int bi = blockIdx.y * BM;
    int bn = blockIdx.x * BN;
    int t = threadIdx.x;
    int tn = (t % (BN / 4)) * 4;
    int ti = (t / (BN / 4)) * 4;
    ull acc2[4][2] = {};
    for (int k0 = 0; k0 < Klen; k0 += BK) {
        for (int e = t; e < BM * BK; e += 256) {
            int i = e / BK, k = e % BK;
            As[i][k] = Ap[(size_t)(bi + i) * lda + k0 + k];
        }
        for (int e = t; e < BK * BN; e += 256) {
            int k = e / BN, n = e % BN;
            Bs[k][n] = Bp[(size_t)(k0 + k) * N + bn + n];
        }
        __syncthreads();
#pragma unroll
        for (int k = 0; k < BK; k++) {
            ulonglong2 b2 = *(const ulonglong2*)&Bs[k][tn];
            ull a0 = pack2(As[ti + 0][k]);
            ull a1 = pack2(As[ti + 1][k]);
            ull a2 = pack2(As[ti + 2][k]);
            ull a3 = pack2(As[ti + 3][k]);
            acc2[0][0] = fma2(a0, b2.x, acc2[0][0]); acc2[0][1] = fma2(a0, b2.y, acc2[0][1]);
            acc2[1][0] = fma2(a1, b2.x, acc2[1][0]); acc2[1][1] = fma2(a1, b2.y, acc2[1][1]);
            acc2[2][0] = fma2(a2, b2.x, acc2[2][0]); acc2[2][1] = fma2(a2, b2.y, acc2[2][1]);
            acc2[3][0] = fma2(a3, b2.x, acc2[3][0]); acc2[3][1] = fma2(a3, b2.y, acc2[3][1]);
        }
        __syncthreads();
    }
#pragma unroll
    for (int r = 0; r < 4; r++) {
        float v0, v1, v2, v3;
        unpack2(acc2[r][0], v0, v1);
        unpack2(acc2[r][1], v2, v3);
        float* dst = Cp + (size_t)(bi + ti + r) * N + bn + tn;
        dst[0] = v0; dst[1] = v1; dst[2] = v2; dst[3] = v3;
    }
}

// ---------------- layer1: add K-partials, write g1, el/er exponentials ----------------
__global__ void elr1_kernel(const float* __restrict__ al, const float* __restrict__ ar) {
    int i = blockIdx.x;
    int t = threadIdx.x;  // 256: warp h handles head h
    float v = g_gp1[(size_t)i * HID + t] + g_gp1[(size_t)(N_NODES + i) * HID + t];
    g_g1[(size_t)i * HID + t] = v;
    float pl = v * al[t & 31];
    float pr = v * ar[t & 31];
#pragma unroll
    for (int o = 16; o; o >>= 1) {
        pl += __shfl_down_sync(0xffffffffu, pl, o);
        pr += __shfl_down_sync(0xffffffffu, pr, o);
    }
    if ((t & 31) == 0) {
        int h = t >> 5;
        float el = pl, er = pr;
        g_eli1[i * H1 + h] = make_float4(-el, __expf(el), __expf(0.2f * el), 0.f);
        g_ebd1[i * H1 + h] = make_float4(er, __expf(er), __expf(0.2f * er), 0.f);
    }
}

// ---------------- layer1 aggregation (no exp; f32x2 FMA) ----------------
__global__ __launch_bounds__(256) void agg1_kernel() {
    __shared__ __align__(16) float w_s[64][128];   // [j][i]
    __shared__ __align__(16) float G_s[64][F1];
    __shared__ float rowsum_s[128];
    int h = blockIdx.x >> 2;
    int p = blockIdx.x & 3;
    int bi = blockIdx.y * 128;
    int t = threadIdx.x;  // 256
    if (t < 128) rowsum_s[t] = 0.f;

    int wi = t & 127;       // weight-phase row
    int whalf = t >> 7;     // which 32-j half
    float4 eli = g_eli1[(bi + wi) * H1 + h];
    float negEl = eli.x, Ai = eli.y, Ci = eli.z;
    int f0 = (t & 7) * 4;
    int i0 = (t >> 3) * 4;
    ull acc2[4][2] = {};
    float lsum = 0.f;
    int jstart = p * (N_NODES / JSPLIT1);

    for (int j0 = jstart; j0 < jstart + N_NODES / JSPLIT1; j0 += 64) {
        __syncthreads();  // previous-iter FMA readers done with w_s/G_s
        // load G chunk [64 j][32 f] as float4
#pragma unroll
        for (int e = t; e < 512; e += 256) {
            int j = e >> 3, q = e & 7;
            ((float4*)G_s[j])[q] = ((const float4*)(g_g1 + (size_t)(j0 + j) * HID + h * F1))[q];
        }
        // weight chunk [64 j][128 i]: separable exp — no MUFU
        unsigned word = g_bits[(bi + wi) * NWORDS + (j0 >> 5) + whalf];
        int jb = whalf * 32;
#pragma unroll 8
        for (int jj = 0; jj < 32; jj++) {
            float4 e4 = g_ebd1[(size_t)(j0 + jb + jj) * H1 + h];  // uniform per warp
            float w = (e4.x > negEl) ? Ai * e4.y : Ci * e4.z;
            w = ((word >> jj) & 1u) ? w : 0.f;
            lsum += w;
            w_s[jb + jj][wi] = w;
        }
        __syncthreads();
        // FMA phase: 8 FFMA2 per 32B of LDS per thread per j
#pragma unroll 8
        for (int jj = 0; jj < 64; jj++) {
            float4 w4 = *(const float4*)&w_s[jj][i0];
            ulonglong2 g2 = *(const ulonglong2*)&G_s[jj][f0];
            ull wr;
            wr = pack2(w4.x); acc2[0][0] = fma2(wr, g2.x, acc2[0][0]); acc2[0][1] = fma2(wr, g2.y, acc2[0][1]);
            wr = pack2(w4.y); acc2[1][0] = fma2(wr, g2.x, acc2[1][0]); acc2[1][1] = fma2(wr, g2.y, acc2[1][1]);
            wr = pack2(w4.z); acc2[2][0] = fma2(wr, g2.x, acc2[2][0]); acc2[2][1] = fma2(wr, g2.y, acc2[2][1]);
            wr = pack2(w4.w); acc2[3][0] = fma2(wr, g2.x, acc2[3][0]); acc2[3][1] = fma2(wr, g2.y, acc2[3][1]);
        }
    }
    atomicAdd(&rowsum_s[wi], lsum);
    __syncthreads();

    size_t base = (size_t)p * N_NODES + bi;
#pragma unroll
    for (int r = 0; r < 4; r++) {
        float v0, v1, v2, v3;
        unpack2(acc2[r][0], v0, v1);
        unpack2(acc2[r][1], v2, v3);
        float* dst = g_n1 + (base + i0 + r) * HID + h * F1 + f0;
        dst[0] = v0; dst[1] = v1; dst[2] = v2; dst[3] = v3;
    }
    if (t < 128) g_d1[(base + t) * H1 + h] = rowsum_s[t];
}

// ---------------- layer1 reduce + divide + ELU ----------------
__global__ void reduce1_kernel() {
    int i = blockIdx.x;
    int t = threadIdx.x;  // 256
    int h = t >> 5;
    float num = 0.f, den = 0.f;
#pragma unroll
    for (int p = 0; p < JSPLIT1; p++) {
        num += g_n1[((size_t)p * N_NODES + i) * HID + t];
        den += g_d1[(p * N_NODES + i) * H1 + h];
    }
    float o = num / den;
    g_h1[(size_t)i * HID + t] = o > 0.f ? o : expm1f(o);
}

// ---------------- layer2: add K-partials, write g2, el/er exponentials ----------------
__global__ void elr2_kernel(const float* __restrict__ al, const float* __restrict__ ar) {
    __shared__ float sl[4], sr[4];
    int i = blockIdx.x;
    int t = threadIdx.x;  // 128
    float v = g_gp2[(size_t)i * OUT_F + t] + g_gp2[(size_t)(N_NODES + i) * OUT_F + t];
    g_g2[(size_t)i * OUT_F + t] = v;
    float pl = v * al[t];
    float pr = v * ar[t];
#pragma unroll
    for (int o = 16; o; o >>= 1) {
        pl += __shfl_down_sync(0xffffffffu, pl, o);
        pr += __shfl_down_sync(0xffffffffu, pr, o);
    }
    if ((t & 31) == 0) { sl[t >> 5] = pl; sr[t >> 5] = pr; }
    __syncthreads();
    if (t == 0) {
        float el = sl[0] + sl[1] + sl[2] + sl[3];
        float er = sr[0] + sr[1] + sr[2] + sr[3];
        g_eli2[i] = make_float4(-el, __expf(el), __expf(0.2f * el), 0.f);
        g_ebd2[i] = make_float4(er, __expf(er), __expf(0.2f * er), 0.f);
    }
}

// ---------------- layer2 aggregation: f32x2 FMA, 8-way j-split ----------------
__global__ __launch_bounds__(256) void agg2_kernel() {
    __shared__ __align__(16) float w_s[32][64];
    __shared__ __align__(16) float G_s[32][OUT_F];
    __shared__ float rowsum_s[64];
    int p = blockIdx.x;        // j partition 0..7
    int bi = blockIdx.y * 64;  // row tile
    int t = threadIdx.x;       // 256
    if (t < 64) rowsum_s[t] = 0.f;

    int wi = t & 63;
    int wq = t >> 6;            // 0..3, 8 j's each
    float4 eli = g_eli2[bi + wi];
    float negEl = eli.x, Ai = eli.y, Ci = eli.z;
    int f0 = (t & 15) * 8;
    int i0 = (t >> 4) * 4;
    ull acc2[4][4] = {};
    float lsum = 0.f;
    int jstart = p * (N_NODES / JSPLIT2);

    for (int j0 = jstart; j0 < jstart + N_NODES / JSPLIT2; j0 += 32) {
        __syncthreads();
#pragma unroll
        for (int e = t; e < 1024; e += 256) {
            int j = e >> 5, q = e & 31;
            ((float4*)G_s[j])[q] = ((const float4*)(g_g2 + (size_t)(j0 + j) * OUT_F))[q];
        }
        unsigned word = g_bits[(bi + wi) * NWORDS + (j0 >> 5)];
        int jb = wq * 8;
#pragma unroll
        for (int jj = 0; jj < 8; jj++) {
            float4 e4 = g_ebd2[j0 + jb + jj];  // uniform per warp
            float w = (e4.x > negEl) ? Ai * e4.y : Ci * e4.z;
            w = ((word >> (jb + jj)) & 1u) ? w : 0.f;
            lsum += w;
            w_s[jb + jj][wi] = w;
        }
        __syncthreads();
#pragma unroll 4
        for (int jj = 0; jj < 32; jj++) {
            float4 w4 = *(const float4*)&w_s[jj][i0];
            ulonglong2 ga = *(const ulonglong2*)&G_s[jj][f0];
            ulonglong2 gb = *(const ulonglong2*)&G_s[jj][f0 + 4];
            ull wr;
            wr = pack2(w4.x);
            acc2[0][0] = fma2(wr, ga.x, acc2[0][0]); acc2[0][1] = fma2(wr, ga.y, acc2[0][1]);
            acc2[0][2] = fma2(wr, gb.x, acc2[0][2]); acc2[0][3] = fma2(wr, gb.y, acc2[0][3]);
            wr = pack2(w4.y);
            acc2[1][0] = fma2(wr, ga.x, acc2[1][0]); acc2[1][1] = fma2(wr, ga.y, acc2[1][1]);
            acc2[1][2] = fma2(wr, gb.x, acc2[1][2]); acc2[1][3] = fma2(wr, gb.y, acc2[1][3]);
            wr = pack2(w4.z);
            acc2[2][0] = fma2(wr, ga.x, acc2[2][0]); acc2[2][1] = fma2(wr, ga.y, acc2[2][1]);
            acc2[2][2] = fma2(wr, gb.x, acc2[2][2]); acc2[2][3] = fma2(wr, gb.y, acc2[2][3]);
            wr = pack2(w4.w);
            acc2[3][0] = fma2(wr, ga.x, acc2[3][0]); acc2[3][1] = fma2(wr, ga.y, acc2[3][1]);
            acc2[3][2] = fma2(wr, gb.x, acc2[3][2]); acc2[3][3] = fma2(wr, gb.y, acc2[3][3]);
        }
    }
    atomicAdd(&rowsum_s[wi], lsum);
    __syncthreads();

#pragma unroll
    for (int r = 0; r < 4; r++) {
        float v[8];
        unpack2(acc2[r][0], v[0], v[1]);
        unpack2(acc2[r][1], v[2], v[3]);
        unpack2(acc2[r][2], v[4], v[5]);
        unpack2(acc2[r][3], v[6], v[7]);
        float* dst = g_part + (size_t)p * N_NODES * OUT_F + (size_t)(bi + i0 + r) * OUT_F + f0;
#pragma unroll
        for (int c = 0; c < 8; c++) dst[c] = v[c];
    }
    if (t < 64) g_psum[p * N_NODES + bi + t] = rowsum_s[t];
}

// ---------------- final reduce + divide ----------------
__global__ void reduce2_kernel(float* __restrict__ out) {
    int i = blockIdx.x;
    int f = threadIdx.x;  // 128
    float num = 0.f, den = 0.f;
#pragma unroll
    for (int p = 0; p < JSPLIT2; p++) {
        num += g_part[(size_t)p * N_NODES * OUT_F + (size_t)i * OUT_F + f];
        den += g_psum[p * N_NODES + i];
    }
    out[i * OUT_F + f] = num / den;
}

// ---------------- launch ----------------
extern "C" void kernel_launch(void* const* d_in, const int* in_sizes, int n_in,
                              void* d_out, int out_size) {
    const float* x    = (const float*)d_in[0];
    const float* W1   = (const float*)d_in[1];
    const float* a1_l = (const float*)d_in[2];
    const float* a1_r = (const float*)d_in[3];
    const float* W2   = (const float*)d_in[4];
    const float* a2_l = (const float*)d_in[5];
    const float* a2_r = (const float*)d_in[6];
    const int*   adj  = (const int*)d_in[7];
    float* out = (float*)d_out;

    float* gp1 = nullptr; float* h1 = nullptr; float* gp2 = nullptr;
    cudaGetSymbolAddress((void**)&gp1, g_gp1);
    cudaGetSymbolAddress((void**)&h1, g_h1);
    cudaGetSymbolAddress((void**)&gp2, g_gp2);

    pack_adj_kernel<<<N_NODES, 256>>>(adj);
    gemm_kernel<64, 64, 16><<<dim3(HID / 64, N_NODES / 64, 2), 256>>>(
        x, W1, gp1, N_NODES, HID, IN_F / 2, IN_F);
    elr1_kernel<<<N_NODES, 256>>>(a1_l, a1_r);
    agg1_kernel<<<dim3(H1 * JSPLIT1, N_NODES / 128), 256>>>();
    reduce1_kernel<<<N_NODES, 256>>>();
    gemm_kernel<64, 64, 16><<<dim3(OUT_F / 64, N_NODES / 64, 2), 256>>>(
        h1, W2, gp2, N_NODES, OUT_F, HID / 2, HID);
    elr2_kernel<<<N_NODES, 128>>>(a2_l, a2_r);
    agg2_kernel<<<dim3(JSPLIT2, N_NODES / 64), 256>>>();
    reduce2_kernel<<<N_NODES, 128>>>(out);
}